// round 2
// baseline (speedup 1.0000x reference)
#include <cuda_runtime.h>

// Problem constants (fixed by the reference setup)
#define Hd   1024
#define Bb   16
#define Ss   512
#define Kk   32
#define Ee   1024
#define NCAT 3072   // node_hidden | Aj | Ai columns

// ---------------- scratch (static device globals; no allocation) ------------
__device__ float g_full_nodes[Bb*Kk*Hd];   // 2 MB
__device__ float g_node_hidden[Bb*Kk*Hd];  // 2 MB
__device__ float g_Aj[Bb*Kk*Hd];           // 2 MB (edge bias folded in)
__device__ float g_Ai[Bb*Kk*Hd];           // 2 MB
__device__ float g_Wcat[Hd*NCAT];          // 12 MB
__device__ float g_cls_hidden[Bb*Hd];
__device__ int   g_n[Bb];

// Accurate fast tanh: err ~1e-7, 2 MUFU + few ALU.
__device__ __forceinline__ float tanh_fast(float x) {
    float e = __expf(2.0f * x);
    return 1.0f - __fdividef(2.0f, e + 1.0f);
}

__device__ __forceinline__ void block_reduce2(float& a0, float& a1, float* red) {
    #pragma unroll
    for (int o = 16; o > 0; o >>= 1) {
        a0 += __shfl_down_sync(0xffffffffu, a0, o);
        a1 += __shfl_down_sync(0xffffffffu, a1, o);
    }
    int w = threadIdx.x >> 5;
    if ((threadIdx.x & 31) == 0) { red[2*w] = a0; red[2*w+1] = a1; }
    __syncthreads();
    if (threadIdx.x == 0) {
        a0 = red[0]; a1 = red[1];
        for (int w2 = 1; w2 < (int)(blockDim.x >> 5); w2++) {
            a0 += red[2*w2]; a1 += red[2*w2+1];
        }
    }
}

// -------- 1. segment means -> full_nodes slots (<n), zeros (>=n); g_n -------
// proof_offsets is int32 (JAX x64-disabled downcasts the int64 numpy array).
__global__ void k_meta(const float* __restrict__ seq, const int* __restrict__ P) {
    int k = blockIdx.x;   // slot 0..31
    int b = blockIdx.y;
    int n = 0;
    #pragma unroll
    for (int j = 0; j < Kk - 1; j++) n += (P[b*Kk + 1 + j] > 0);
    if (k == 0 && threadIdx.x == 0) g_n[b] = n;
    float* dst = &g_full_nodes[(b*Kk + k)*Hd];
    if (k < n) {
        int end   = P[b*Kk + 1 + k];
        int start = (k == 0) ? 1 : (P[b*Kk + k] + 1);
        float inv = 1.0f / (float)(end - start + 1);
        #pragma unroll
        for (int u = 0; u < Hd/256; u++) {
            int h = threadIdx.x + u*256;
            float s = 0.0f;
            for (int p = start; p <= end; p++)
                s += seq[((long)b*Ss + p)*Hd + h];
            dst[h] = s * inv;
        }
    } else {
        #pragma unroll
        for (int u = 0; u < Hd/256; u++) dst[threadIdx.x + u*256] = 0.0f;
    }
}

// -------- 2. build Wcat = [node_dense_W | W0+W2 | W1-W2] --------------------
__global__ void k_build_wcat(const float* __restrict__ nodeW, const float* __restrict__ eW) {
    int idx = blockIdx.x*256 + threadIdx.x;          // < Hd*NCAT
    int kk = idx / NCAT;
    int c  = idx - kk*NCAT;
    float v;
    if (c < Hd) {
        v = nodeW[kk*Hd + c];
    } else if (c < 2*Hd) {
        int h = c - Hd;
        v = eW[kk*Hd + h] + eW[(2*Hd + kk)*Hd + h];           // W0 + W2 (acts on n_j)
    } else {
        int h = c - 2*Hd;
        v = eW[(Hd + kk)*Hd + h] - eW[(2*Hd + kk)*Hd + h];    // W1 - W2 (acts on n_i)
    }
    g_Wcat[idx] = v;
}

// -------- 3. naf = cls_tok @ naf_W + naf_b  -> full_nodes[b, n[b], :] -------
__global__ void k_gemv_naf(const float* __restrict__ seq, const float* __restrict__ Wf,
                           const float* __restrict__ bias) {
    __shared__ float xs[Hd];
    int b = blockIdx.y;
    const float* x = seq + (long)b*Ss*Hd;   // row 0 = cls token
    #pragma unroll
    for (int u = 0; u < Hd/128; u++) xs[threadIdx.x + u*128] = x[threadIdx.x + u*128];
    __syncthreads();
    int col = blockIdx.x*128 + threadIdx.x;
    float a0=0.f, a1=0.f, a2=0.f, a3=0.f;
    for (int kk = 0; kk < Hd; kk += 4) {
        a0 = fmaf(xs[kk  ], Wf[(kk  )*Hd + col], a0);
        a1 = fmaf(xs[kk+1], Wf[(kk+1)*Hd + col], a1);
        a2 = fmaf(xs[kk+2], Wf[(kk+2)*Hd + col], a2);
        a3 = fmaf(xs[kk+3], Wf[(kk+3)*Hd + col], a3);
    }
    float acc = (a0 + a1) + (a2 + a3) + bias[col];
    int n = g_n[b];
    g_full_nodes[(b*Kk + n)*Hd + col] = acc;
}

// -------- 4. cls hidden = tanh(cls_tok @ cls_dense_W + b) -------------------
__global__ void k_cls_hidden(const float* __restrict__ seq, const float* __restrict__ Wf,
                             const float* __restrict__ bias) {
    __shared__ float xs[Hd];
    int b = blockIdx.y;
    const float* x = seq + (long)b*Ss*Hd;
    #pragma unroll
    for (int u = 0; u < Hd/128; u++) xs[threadIdx.x + u*128] = x[threadIdx.x + u*128];
    __syncthreads();
    int col = blockIdx.x*128 + threadIdx.x;
    float a0=0.f, a1=0.f, a2=0.f, a3=0.f;
    for (int kk = 0; kk < Hd; kk += 4) {
        a0 = fmaf(xs[kk  ], Wf[(kk  )*Hd + col], a0);
        a1 = fmaf(xs[kk+1], Wf[(kk+1)*Hd + col], a1);
        a2 = fmaf(xs[kk+2], Wf[(kk+2)*Hd + col], a2);
        a3 = fmaf(xs[kk+3], Wf[(kk+3)*Hd + col], a3);
    }
    g_cls_hidden[b*Hd + col] = tanh_fast((a0 + a1) + (a2 + a3) + bias[col]);
}

// -------- 5. cls logits -> out[0:32] ----------------------------------------
__global__ void k_cls_out(const float* __restrict__ oW, const float* __restrict__ ob,
                          float* __restrict__ out) {
    __shared__ float red[8];
    int b = blockIdx.x;
    float a0 = 0.f, a1 = 0.f;
    #pragma unroll
    for (int u = 0; u < Hd/128; u++) {
        int h = threadIdx.x + u*128;
        float t = g_cls_hidden[b*Hd + h];
        a0 = fmaf(t, oW[2*h  ], a0);
        a1 = fmaf(t, oW[2*h+1], a1);
    }
    block_reduce2(a0, a1, red);
    if (threadIdx.x == 0) {
        out[b*2]     = a0 + ob[0];
        out[b*2 + 1] = a1 + ob[1];
    }
}

// -------- 6. fused GEMM: full_nodes(512x1024) @ Wcat(1024x3072) -------------
// BM=128, BN=64, BK=16, 256 threads, 8x4 micro-tile. Grid (48, 4) = 192 blocks.
__global__ __launch_bounds__(256) void k_gemm_fused(const float* __restrict__ node_b,
                                                    const float* __restrict__ edge_b) {
    __shared__ float As[16][128];   // transposed: [k][m]
    __shared__ float Bs[16][64];    // [k][n]
    int bn = blockIdx.x, bm = blockIdx.y;
    int tid = threadIdx.x;
    int tm = tid >> 4, tn = tid & 15;
    float acc[8][4];
    #pragma unroll
    for (int i = 0; i < 8; i++)
        #pragma unroll
        for (int j = 0; j < 4; j++) acc[i][j] = 0.0f;

    const int arow_base = bm * 128;
    for (int kt = 0; kt < Hd; kt += 16) {
        #pragma unroll
        for (int i = 0; i < 2; i++) {
            int f   = tid*2 + i;        // 0..511 float4s of the 128x16 A tile
            int row = f >> 2;
            int kk  = (f & 3) * 4;
            const float4 v = *(const float4*)&g_full_nodes[(arow_base + row)*Hd + kt + kk];
            As[kk  ][row] = v.x;
            As[kk+1][row] = v.y;
            As[kk+2][row] = v.z;
            As[kk+3][row] = v.w;
        }
        {
            int kr = tid >> 4;
            int nn = (tid & 15) * 4;
            *(float4*)&Bs[kr][nn] = *(const float4*)&g_Wcat[(kt + kr)*NCAT + bn*64 + nn];
        }
        __syncthreads();
        #pragma unroll
        for (int k = 0; k < 16; k++) {
            float4 av0 = *(const float4*)&As[k][tm*8];
            float4 av1 = *(const float4*)&As[k][tm*8 + 4];
            float4 bv  = *(const float4*)&Bs[k][tn*4];
            float a[8] = {av0.x, av0.y, av0.z, av0.w, av1.x, av1.y, av1.z, av1.w};
            float bb[4] = {bv.x, bv.y, bv.z, bv.w};
            #pragma unroll
            for (int i = 0; i < 8; i++)
                #pragma unroll
                for (int j = 0; j < 4; j++)
                    acc[i][j] = fmaf(a[i], bb[j], acc[i][j]);
        }
        __syncthreads();
    }
    int region = bn >> 4;        // 0: node hidden, 1: Aj, 2: Ai (BN=64 divides 1024)
    int cbase  = bn*64 + tn*4;
    #pragma unroll
    for (int i = 0; i < 8; i++) {
        int r = arow_base + tm*8 + i;
        #pragma unroll
        for (int j = 0; j < 4; j++) {
            int c = cbase + j;
            float v = acc[i][j];
            if (region == 0) {
                g_node_hidden[r*Hd + c] = tanh_fast(v + node_b[c]);
            } else if (region == 1) {
                int h = c - Hd;
                g_Aj[r*Hd + h] = v + edge_b[h];   // fold edge bias into Aj
            } else {
                int h = c - 2*Hd;
                g_Ai[r*Hd + h] = v;
            }
        }
    }
}

// -------- 7. node logits -> out[32 : 32+1024] -------------------------------
__global__ void k_node_out(const float* __restrict__ oW, const float* __restrict__ ob,
                           float* __restrict__ out) {
    __shared__ float red[8];
    int r = blockIdx.x;   // 0..511 = b*32 + k
    float a0 = 0.f, a1 = 0.f;
    #pragma unroll
    for (int u = 0; u < Hd/128; u++) {
        int h = threadIdx.x + u*128;
        float t = g_node_hidden[r*Hd + h];
        a0 = fmaf(t, oW[2*h  ], a0);
        a1 = fmaf(t, oW[2*h+1], a1);
    }
    block_reduce2(a0, a1, red);
    if (threadIdx.x == 0) {
        out[32 + r*2]     = a0 + ob[0];
        out[32 + r*2 + 1] = a1 + ob[1];
    }
}

// -------- 8. edge logits -> out[1056 : 33824] -------------------------------
__global__ void k_edge(const float* __restrict__ eb, const float* __restrict__ oW,
                       const float* __restrict__ ob, float* __restrict__ out) {
    __shared__ float red[8];
    int e = blockIdx.x, b = blockIdx.y;
    int m = g_n[b] + 1;
    bool valid = e < m*m;
    int i = min(e / m, Kk - 1);
    int j = min(e % m, Kk - 1);
    const float* aj = &g_Aj[(b*Kk + j)*Hd];   // has edge bias folded in
    const float* ai = &g_Ai[(b*Kk + i)*Hd];
    float a0 = 0.f, a1 = 0.f;
    #pragma unroll
    for (int u = 0; u < Hd/128; u++) {
        int h = threadIdx.x + u*128;
        float pre = valid ? (aj[h] + ai[h]) : eb[h];  // invalid: tanh(bias) path
        float t = tanh_fast(pre);
        a0 = fmaf(t, oW[2*h  ], a0);
        a1 = fmaf(t, oW[2*h+1], a1);
    }
    block_reduce2(a0, a1, red);
    if (threadIdx.x == 0) {
        long base = 32 + Bb*Kk*2 + ((long)b*Ee + e)*2;
        out[base]     = a0 + ob[0];
        out[base + 1] = a1 + ob[1];
    }
}

// ---------------------------------------------------------------------------
extern "C" void kernel_launch(void* const* d_in, const int* in_sizes, int n_in,
                              void* d_out, int out_size) {
    const float* seq   = (const float*)d_in[0];
    const int*   P     = (const int*)d_in[1];     // int32! (JAX x64 disabled)
    const float* nafW  = (const float*)d_in[2];
    const float* nafb  = (const float*)d_in[3];
    const float* clsW  = (const float*)d_in[4];
    const float* clsb  = (const float*)d_in[5];
    const float* clsoW = (const float*)d_in[6];
    const float* clsob = (const float*)d_in[7];
    const float* ndW   = (const float*)d_in[8];
    const float* ndb   = (const float*)d_in[9];
    const float* noW   = (const float*)d_in[10];
    const float* nob   = (const float*)d_in[11];
    const float* edW   = (const float*)d_in[12];
    const float* edb   = (const float*)d_in[13];
    const float* eoW   = (const float*)d_in[14];
    const float* eob   = (const float*)d_in[15];
    float* out = (float*)d_out;

    k_meta<<<dim3(Kk, Bb), 256>>>(seq, P);
    k_build_wcat<<<(Hd*NCAT)/256, 256>>>(ndW, edW);
    k_gemv_naf<<<dim3(Hd/128, Bb), 128>>>(seq, nafW, nafb);
    k_cls_hidden<<<dim3(Hd/128, Bb), 128>>>(seq, clsW, clsb);
    k_cls_out<<<Bb, 128>>>(clsoW, clsob, out);
    k_gemm_fused<<<dim3(NCAT/64, (Bb*Kk)/128), 256>>>(ndb, edb);
    k_node_out<<<Bb*Kk, 128>>>(noW, nob, out);
    k_edge<<<dim3(Ee, Bb), 128>>>(edb, eoW, eob, out);
}